// round 10
// baseline (speedup 1.0000x reference)
#include <cuda_runtime.h>
#include <cuda_bf16.h>

// src [8,16,512,512] f32, flow [8,2,512,512] f32, out [8,16,512,512] f32.
//
// Index math reproduces XLA's lowering bit-exactly (reciprocal rewrite of /511,
// fp32-rounded intermediates, no FMA contraction, rint half-to-even, border
// clamp). Verified rel_err == 0.0 in R3-R9.
//
// R10: pipelined smem band-staging.
//  - CTA = (batch, 16-row band, channel-half); grid 512, 2 CTAs/SM (107.5KB smem).
//  - Per-pixel local gather index precomputed once (ushort smem); out-of-window
//    pixels (P~4.7e-4) go to a smem fixup list -> hot loop is branch-free.
//  - cp.async.cg ping-pong: channel c+1 streams into buffer B while buffer A is
//    scatter-consumed. DRAM stays saturated; scatter hides under the copy.

#define B 8
#define C 16
#define H 512
#define W 512
#define HW (H * W)
#define W_BITS 9
#define R 16                  // output rows per CTA band
#define G 3                   // guard rows each side
#define SROWS (R + 2 * G)     // 22 staged rows
#define TPB 256
#define CSPLIT 2
#define CPC (C / CSPLIT)      // 8 channels per CTA
#define PX_PER_CTA (R * W)    // 8192
#define STAGE_FLOATS (SROWS * W)          // 11264
#define CHUNKS (STAGE_FLOATS / 4)         // 2816 16B chunks
#define CHUNKS_PT (CHUNKS / TPB)          // 11
#define FB_CAP 512

#define SMEM_BYTES (2 * STAGE_FLOATS * 4 + PX_PER_CTA * 2 + 4 + FB_CAP * 2)

__device__ __forceinline__ int ref_index(float coord, float disp)
{
    const float rcp = 1.0f / 511.0f;
    float t = __fadd_rn(coord, disp);
    t = __fmul_rn(t, rcp);
    t = __fadd_rn(t, -0.5f);
    t = __fmul_rn(2.0f, t);
    t = __fadd_rn(t, 1.0f);
    t = __fmul_rn(t, 0.5f);
    t = __fmul_rn(t, 511.0f);
    int i = __float2int_rn(t);
    return min(max(i, 0), 511);
}

__device__ __forceinline__ void cp_async16(void* smem_dst, const void* gmem_src)
{
    unsigned s = (unsigned)__cvta_generic_to_shared(smem_dst);
    asm volatile("cp.async.cg.shared.global [%0], [%1], 16;\n"
                 :: "r"(s), "l"(gmem_src));
}
__device__ __forceinline__ void cp_commit()
{
    asm volatile("cp.async.commit_group;\n");
}
__device__ __forceinline__ void cp_wait_all()
{
    asm volatile("cp.async.wait_group 0;\n");
}

__device__ __forceinline__ void issue_stage(float* buf, const float* sb,
                                            int ylo, int tid)
{
    #pragma unroll
    for (int j = 0; j < CHUNKS_PT; ++j) {        // 11 x 16B per thread
        int q    = tid + j * TPB;                // chunk id
        int row  = q >> 7;                       // 128 chunks per row
        int ysrc = min(max(ylo + row, 0), H - 1);
        cp_async16(buf + q * 4, sb + ysrc * W + (q & 127) * 4);
    }
    cp_commit();
}

__global__ __launch_bounds__(TPB, 2) void flow_warp_pipe_kernel(
    const float* __restrict__ src,
    const float* __restrict__ flow,
    float* __restrict__ out)
{
    extern __shared__ char smem_raw[];
    float* stage0 = (float*)smem_raw;                             // 44 KB
    float* stage1 = stage0 + STAGE_FLOATS;                        // 44 KB
    unsigned short* lin16 = (unsigned short*)(stage1 + STAGE_FLOATS); // 16 KB
    int* fb_cnt = (int*)(lin16 + PX_PER_CTA);
    unsigned short* fb_px = (unsigned short*)(fb_cnt + 1);

    int bid  = blockIdx.x;                // [0, 512)
    int half = bid & 1;
    int band = (bid >> 1) & 31;
    int b    = bid >> 6;
    int h0   = band * R;
    int ylo  = h0 - G;
    int tid  = threadIdx.x;
    int c0   = half * CPC;

    const float* sb_base = src + (size_t)b * C * HW;
    float*       ob_base = out + (size_t)b * C * HW + (size_t)h0 * W;
    const float* fb      = flow + (size_t)b * 2 * HW;

    if (tid == 0) *fb_cnt = 0;
    __syncthreads();

    // Prologue: start channel c0 stage copies immediately (overlaps phase A).
    issue_stage(stage0, sb_base + c0 * HW, ylo, tid);

    // Phase A: per-pixel local gather index (once, reused for all channels).
    #pragma unroll 4
    for (int px = tid; px < PX_PER_CTA; px += TPB) {
        int h = h0 + (px >> W_BITS);
        int w = px & (W - 1);
        float f0 = __ldcs(fb + h * W + w);
        float f1 = __ldcs(fb + HW + h * W + w);
        int yi = ref_index((float)h, f0);
        int xi = ref_index((float)w, f1);
        int dy = yi - ylo;
        if ((unsigned)dy < SROWS) {
            lin16[px] = (unsigned short)((dy << W_BITS) | xi);
        } else {                              // rare: P ~ 4.7e-4
            lin16[px] = 0;                    // placeholder, fixed up later
            int slot = atomicAdd(fb_cnt, 1);
            if (slot < FB_CAP) fb_px[slot] = (unsigned short)px;
        }
    }
    __syncthreads();
    int nfb = min(*fb_cnt, FB_CAP);

    for (int cc = 0; cc < CPC; ++cc) {
        float* cur = (cc & 1) ? stage1 : stage0;
        float* nxt = (cc & 1) ? stage0 : stage1;

        cp_wait_all();                        // channel cc's copies landed
        __syncthreads();                      // visible to all threads; prev
                                              // scatter also fully done
        if (cc + 1 < CPC)                     // stream channel cc+1 while we
            issue_stage(nxt, sb_base + (c0 + cc + 1) * HW, ylo, tid); // consume cc

        // Branch-free scatter: LDS index -> LDS value -> coalesced streaming STG.
        float* ob = ob_base + (c0 + cc) * HW;
        #pragma unroll
        for (int k = 0; k < PX_PER_CTA / TPB; ++k) {     // 32 iters
            int px = tid + k * TPB;
            __stcs(ob + px, cur[lin16[px]]);
        }

        // Fixup the out-of-window pixels with the exact global gather.
        if (nfb) {
            __syncthreads();                  // order: main STG before overwrite
            if (tid < nfb) {
                int px = fb_px[tid];
                int h = h0 + (px >> W_BITS);
                int w = px & (W - 1);
                float f0 = __ldg(fb + h * W + w);
                float f1 = __ldg(fb + HW + h * W + w);
                int yi = ref_index((float)h, f0);
                int xi = ref_index((float)w, f1);
                ob[px] = __ldg(sb_base + (c0 + cc) * HW + yi * W + xi);
            }
        }
    }
}

extern "C" void kernel_launch(void* const* d_in, const int* in_sizes, int n_in,
                              void* d_out, int out_size)
{
    const float* src  = (const float*)d_in[0];
    const float* flow = (const float*)d_in[1];
    float*       out  = (float*)d_out;

    cudaFuncSetAttribute(flow_warp_pipe_kernel,
                         cudaFuncAttributeMaxDynamicSharedMemorySize, SMEM_BYTES);

    int blocks = B * (H / R) * CSPLIT;    // 512
    flow_warp_pipe_kernel<<<blocks, TPB, SMEM_BYTES>>>(src, flow, out);
}

// round 11
// speedup vs baseline: 1.6494x; 1.6494x over previous
#include <cuda_runtime.h>
#include <cuda_bf16.h>

// src [8,16,512,512] f32, flow [8,2,512,512] f32, out [8,16,512,512] f32.
//
// Index math reproduces XLA's lowering bit-exactly (reciprocal-constant rewrite
// of /511, fp32-rounded intermediates, no FMA contraction, rint half-to-even,
// border clamp). Verified rel_err == 0.0 in R3-R10.
//
// R11: direct-gather (best family), tuned for LSU issue cost:
//  - 4 px/thread -> per channel 4 gather LDG.32 + ONE STG.128 (store issue
//    12 cyc/4px instead of 20), no staging array so regs stay ~38.
//  - __launch_bounds__(256,6): 48 warps/SM, 75% occupancy.
//  - flow read as 2x LDG.128; streaming hints on flow/out keep L2 for src.

#define B 8
#define C 16
#define H 512
#define W 512
#define HW (H * W)          // 1<<18
#define HW_BITS 18
#define W_BITS 9

__device__ __forceinline__ int ref_index(float coord, float disp)
{
    const float rcp = 1.0f / 511.0f;         // fp32(1/511), XLA recip rewrite
    float t = __fadd_rn(coord, disp);        // ii + flow
    t = __fmul_rn(t, rcp);                   // * (1/511)
    t = __fadd_rn(t, -0.5f);                 // - 0.5
    t = __fmul_rn(2.0f, t);                  // * 2 (exact)
    t = __fadd_rn(t, 1.0f);                  // + 1
    t = __fmul_rn(t, 0.5f);                  // * 0.5 (exact)
    t = __fmul_rn(t, 511.0f);                // * 511
    int i = __float2int_rn(t);               // round half-to-even
    return min(max(i, 0), 511);              // border clamp
}

__global__ __launch_bounds__(256, 6) void flow_warp_v4s_kernel(
    const float* __restrict__ src,
    const float* __restrict__ flow,
    float* __restrict__ out)
{
    int t = blockIdx.x * blockDim.x + threadIdx.x;   // over B*HW/4
    int b   = t >> (HW_BITS - 2);
    int hw4 = (t & ((HW >> 2) - 1)) << 2;            // base pixel, multiple of 4
    int h   = hw4 >> W_BITS;
    int w   = hw4 & (W - 1);

    const float* fb = flow + (size_t)b * 2 * HW;
    float4 fy = __ldcs((const float4*)(fb + hw4));        // row disp, 4 px
    float4 fx = __ldcs((const float4*)(fb + HW + hw4));   // col disp, 4 px

    float hf = (float)h;
    int lin0 = (ref_index(hf, fy.x) << W_BITS) + ref_index((float)(w + 0), fx.x);
    int lin1 = (ref_index(hf, fy.y) << W_BITS) + ref_index((float)(w + 1), fx.y);
    int lin2 = (ref_index(hf, fy.z) << W_BITS) + ref_index((float)(w + 2), fx.z);
    int lin3 = (ref_index(hf, fy.w) << W_BITS) + ref_index((float)(w + 3), fx.w);

    const float* sb = src + (size_t)b * C * HW;
    float*       ob = out + (size_t)b * C * HW;

    #pragma unroll
    for (int c = 0; c < C; ++c) {
        const float* s = sb + c * HW;
        float4 v;
        v.x = __ldg(s + lin0);
        v.y = __ldg(s + lin1);
        v.z = __ldg(s + lin2);
        v.w = __ldg(s + lin3);
        __stcs((float4*)(ob + c * HW + hw4), v);   // one STG.128 per channel
    }
}

extern "C" void kernel_launch(void* const* d_in, const int* in_sizes, int n_in,
                              void* d_out, int out_size)
{
    const float* src  = (const float*)d_in[0];
    const float* flow = (const float*)d_in[1];
    float*       out  = (float*)d_out;

    int total = (B * HW) >> 2;          // 524,288 threads (4 px each)
    int threads = 256;
    int blocks = total / threads;       // 2048
    flow_warp_v4s_kernel<<<blocks, threads>>>(src, flow, out);
}

// round 12
// speedup vs baseline: 1.9177x; 1.1627x over previous
#include <cuda_runtime.h>
#include <cuda_bf16.h>

// src [8,16,512,512] f32, flow [8,2,512,512] f32, out [8,16,512,512] f32.
//
// Index math reproduces XLA's lowering bit-exactly (reciprocal-constant rewrite
// of /511, fp32-rounded intermediates, no FMA contraction, rint half-to-even,
// border clamp). Verified rel_err == 0.0 in R3-R11.
//
// R12 = R6 (best family: 1 px/thread, 32 regs, 8 CTA/SM) with ONE change:
// CTA tiling 256 linear px of one row  ->  32(x) x 8(h) 2D tile.
// The 8 vertically-stacked warps gather from the same src rows (flow jitter
// +/-3), so gather lines are L1-resident and reused ~8x16 times -> gather
// service latency drops from L2 (~250cyc) toward L1 (~39cyc), raising
// throughput at the fixed outstanding-LDG cap.

#define B 8
#define C 16
#define H 512
#define W 512
#define HW (H * W)          // 1<<18
#define W_BITS 9

#define TILE_X 32           // lanes: consecutive x (coalesced)
#define TILE_H 8            // warps: consecutive rows (L1 line sharing)
#define XT (W / TILE_X)     // 16 x-tiles
#define HT (H / TILE_H)     // 64 h-tiles

__device__ __forceinline__ int ref_index(float coord, float disp)
{
    const float rcp = 1.0f / 511.0f;         // fp32(1/511), XLA recip rewrite
    float t = __fadd_rn(coord, disp);        // ii + flow
    t = __fmul_rn(t, rcp);                   // * (1/511)
    t = __fadd_rn(t, -0.5f);                 // - 0.5
    t = __fmul_rn(2.0f, t);                  // * 2 (exact)
    t = __fadd_rn(t, 1.0f);                  // + 1
    t = __fmul_rn(t, 0.5f);                  // * 0.5 (exact)
    t = __fmul_rn(t, 511.0f);                // * 511
    int i = __float2int_rn(t);               // round half-to-even
    return min(max(i, 0), 511);              // border clamp
}

__global__ __launch_bounds__(256, 8) void flow_warp_tile_kernel(
    const float* __restrict__ src,
    const float* __restrict__ flow,
    float* __restrict__ out)
{
    int bidx = blockIdx.x;
    int xt = bidx & (XT - 1);               // x-tile
    int ht = (bidx >> 4) & (HT - 1);        // h-tile
    int b  = bidx >> 10;                    // batch

    int lane = threadIdx.x & 31;
    int wrp  = threadIdx.x >> 5;            // 0..7 -> row within tile

    int h  = ht * TILE_H + wrp;
    int w  = xt * TILE_X + lane;
    int hw = (h << W_BITS) + w;

    const float* fb = flow + (size_t)b * 2 * HW;
    float f0 = __ldcs(fb + hw);             // row displacement (streamed)
    float f1 = __ldcs(fb + HW + hw);        // col displacement (streamed)

    int yi = ref_index((float)h, f0);
    int xi = ref_index((float)w, f1);
    int lin = (yi << W_BITS) + xi;

    const float* sb = src + (size_t)b * C * HW;
    float*       ob = out + (size_t)b * C * HW;

    #pragma unroll
    for (int c = 0; c < C; ++c) {
        __stcs(ob + c * HW + hw, __ldg(sb + c * HW + lin));
    }
}

extern "C" void kernel_launch(void* const* d_in, const int* in_sizes, int n_in,
                              void* d_out, int out_size)
{
    const float* src  = (const float*)d_in[0];
    const float* flow = (const float*)d_in[1];
    float*       out  = (float*)d_out;

    int blocks = B * HT * XT;              // 8192, same as R6
    flow_warp_tile_kernel<<<blocks, 256>>>(src, flow, out);
}

// round 13
// speedup vs baseline: 1.9886x; 1.0370x over previous
#include <cuda_runtime.h>
#include <cuda_bf16.h>

// src [8,16,512,512] f32, flow [8,2,512,512] f32, out [8,16,512,512] f32.
//
// Index math reproduces XLA's lowering bit-exactly (reciprocal-constant rewrite
// of /511, fp32-rounded intermediates, no FMA contraction, rint half-to-even,
// border clamp). Verified rel_err == 0.0 in R3-R12.
//
// R13 = R12 with the locality lever doubled: 32(x) x 16(h) tile, 512 threads,
// still 1 px/thread. Vertical gather overfetch drops 2.0x -> 1.5x and 16
// stacked warps share L1-resident src lines. Occupancy unchanged:
// 16 warps x 4 CTAs/SM = 64 warps/SM at 32 regs.

#define B 8
#define C 16
#define H 512
#define W 512
#define HW (H * W)          // 1<<18
#define W_BITS 9

#define TILE_X 32           // lanes: consecutive x (coalesced)
#define TILE_H 16           // warps: consecutive rows (L1 line sharing)
#define TPB (TILE_X * TILE_H)   // 512
#define XT (W / TILE_X)     // 16 x-tiles
#define HT (H / TILE_H)     // 32 h-tiles

__device__ __forceinline__ int ref_index(float coord, float disp)
{
    const float rcp = 1.0f / 511.0f;         // fp32(1/511), XLA recip rewrite
    float t = __fadd_rn(coord, disp);        // ii + flow
    t = __fmul_rn(t, rcp);                   // * (1/511)
    t = __fadd_rn(t, -0.5f);                 // - 0.5
    t = __fmul_rn(2.0f, t);                  // * 2 (exact)
    t = __fadd_rn(t, 1.0f);                  // + 1
    t = __fmul_rn(t, 0.5f);                  // * 0.5 (exact)
    t = __fmul_rn(t, 511.0f);                // * 511
    int i = __float2int_rn(t);               // round half-to-even
    return min(max(i, 0), 511);              // border clamp
}

__global__ __launch_bounds__(TPB, 4) void flow_warp_tile16_kernel(
    const float* __restrict__ src,
    const float* __restrict__ flow,
    float* __restrict__ out)
{
    int bidx = blockIdx.x;
    int xt = bidx & (XT - 1);               // x-tile
    int ht = (bidx >> 4) & (HT - 1);        // h-tile
    int b  = bidx >> 9;                     // batch (16*32 = 512 tiles/img)

    int lane = threadIdx.x & 31;
    int wrp  = threadIdx.x >> 5;            // 0..15 -> row within tile

    int h  = ht * TILE_H + wrp;
    int w  = xt * TILE_X + lane;
    int hw = (h << W_BITS) + w;

    const float* fb = flow + (size_t)b * 2 * HW;
    float f0 = __ldcs(fb + hw);             // row displacement (streamed)
    float f1 = __ldcs(fb + HW + hw);        // col displacement (streamed)

    int yi = ref_index((float)h, f0);
    int xi = ref_index((float)w, f1);
    int lin = (yi << W_BITS) + xi;

    const float* sb = src + (size_t)b * C * HW;
    float*       ob = out + (size_t)b * C * HW;

    #pragma unroll
    for (int c = 0; c < C; ++c) {
        __stcs(ob + c * HW + hw, __ldg(sb + c * HW + lin));
    }
}

extern "C" void kernel_launch(void* const* d_in, const int* in_sizes, int n_in,
                              void* d_out, int out_size)
{
    const float* src  = (const float*)d_in[0];
    const float* flow = (const float*)d_in[1];
    float*       out  = (float*)d_out;

    int blocks = B * HT * XT;              // 8 * 32 * 16 = 4096
    flow_warp_tile16_kernel<<<blocks, TPB>>>(src, flow, out);
}